// round 14
// baseline (speedup 1.0000x reference)
#include <cuda_runtime.h>
#include <cuda_bf16.h>
#include <cstdint>

// LocalAttention B=8,H=8,T=8192,E=64; 128 buckets of 64; window = prev+cur bucket.
// HMMA bf16 3-pass split, streaming flash loop. Two buckets per 256-thread CTA
// (192-row shared K/V slab), 2 CTAs/SM (16 warps). Diagonal-only masking,
// fused exp->pack, affine precomputed LDSM addresses (swizzle XOR is lane-const).

#define SWZ(o) ((o) ^ (((o) >> 3) & 0x70))

// smem planes: 192 rows x 128B each; lo plane = hi plane + 24576
#define OKH 0
#define OKL 24576
#define OVH 49152
#define OVL 73728
#define SMEM_BYTES 98304

static __device__ __forceinline__ uint32_t cvta_s(const void* p) {
    uint32_t a;
    asm("{ .reg .u64 t; cvta.to.shared.u64 t, %1; cvt.u32.u64 %0, t; }" : "=r"(a) : "l"(p));
    return a;
}
static __device__ __forceinline__ uint32_t pkbf2(float lo, float hi) {  // first arg -> low half
    uint32_t r;
    asm("cvt.rn.bf16x2.f32 %0, %1, %2;" : "=r"(r) : "f"(hi), "f"(lo));
    return r;
}

#define LDSM4(r0,r1,r2,r3,a) \
    asm("ldmatrix.sync.aligned.m8n8.x4.shared.b16 {%0,%1,%2,%3}, [%4];" \
        : "=r"(r0),"=r"(r1),"=r"(r2),"=r"(r3) : "r"(a) : "memory")
#define LDSM4T(r0,r1,r2,r3,a) \
    asm("ldmatrix.sync.aligned.m8n8.x4.trans.shared.b16 {%0,%1,%2,%3}, [%4];" \
        : "=r"(r0),"=r"(r1),"=r"(r2),"=r"(r3) : "r"(a) : "memory")
#define MMA(d,a0,a1,a2,a3,b0,b1) \
    asm("mma.sync.aligned.m16n8k16.row.col.f32.bf16.bf16.f32 " \
        "{%0,%1,%2,%3},{%4,%5,%6,%7},{%8,%9},{%0,%1,%2,%3};" \
        : "+f"((d)[0]),"+f"((d)[1]),"+f"((d)[2]),"+f"((d)[3]) \
        : "r"(a0),"r"(a1),"r"(a2),"r"(a3),"r"(b0),"r"(b1))

static __device__ __forceinline__ void split2(float2 f, uint32_t& h, uint32_t& l) {
    h = pkbf2(f.x, f.y);
    l = pkbf2(f.x - __uint_as_float(h << 16), f.y - __uint_as_float(h & 0xffff0000u));
}
static __device__ __forceinline__ void wr_hilo(char* smp, uint32_t off, int oh, int ol,
                                               float4 f0, float4 f1) {
    uint32_t h0 = pkbf2(f0.x, f0.y), h1 = pkbf2(f0.z, f0.w);
    uint32_t h2 = pkbf2(f1.x, f1.y), h3 = pkbf2(f1.z, f1.w);
    uint32_t L0 = pkbf2(f0.x - __uint_as_float(h0 << 16), f0.y - __uint_as_float(h0 & 0xffff0000u));
    uint32_t L1 = pkbf2(f0.z - __uint_as_float(h1 << 16), f0.w - __uint_as_float(h1 & 0xffff0000u));
    uint32_t L2 = pkbf2(f1.x - __uint_as_float(h2 << 16), f1.y - __uint_as_float(h2 & 0xffff0000u));
    uint32_t L3 = pkbf2(f1.z - __uint_as_float(h3 << 16), f1.w - __uint_as_float(h3 & 0xffff0000u));
    *(uint4*)(smp + oh + off) = make_uint4(h0, h1, h2, h3);
    *(uint4*)(smp + ol + off) = make_uint4(L0, L1, L2, L3);
}

__global__ __launch_bounds__(256, 2)
void local_attn_hmma(const float* __restrict__ q, const float* __restrict__ k,
                     const float* __restrict__ v, float* __restrict__ out)
{
    extern __shared__ char smc[];
    const uint32_t sb = cvta_s(smc);
    const int tid = threadIdx.x, lane = tid & 31, wp = tid >> 5;
    const int pw = blockIdx.x, bh = blockIdx.y;
    const size_t base = (size_t)bh * (8192 * 64);

    const int b  = wp >> 2;             // bucket within pair (0/1)
    const int wq = wp & 3;              // warp within bucket
    const int t2 = (lane & 3) * 2;
    const int lr = lane >> 2;
    const int r0 = wq * 16 + lr, r1 = r0 + 8;   // local q rows (0..63)
    const int nlim = wq + 5;            // causal: chunks ks < wq+5; ks==nlim-1 is diagonal
    const bool wok = (pw > 0) || (b > 0);

    // diagonal-chunk masks (chunk-invariant)
    const bool d00 = (t2     <= lr);
    const bool d01 = (t2 + 1 <= lr);

    // ---- Q fragments straight from global, hi/lo split ----
    uint32_t qh[4][4], ql[4][4];
    {
        const float* gq = q + base + (size_t)(pw * 128 + b * 64) * 64;
        const float* p0 = gq + r0 * 64 + t2;
        const float* p1 = gq + r1 * 64 + t2;
        #pragma unroll
        for (int ke = 0; ke < 4; ++ke) {
            split2(*(const float2*)(p0 + ke * 16),     qh[ke][0], ql[ke][0]);
            split2(*(const float2*)(p1 + ke * 16),     qh[ke][1], ql[ke][1]);
            split2(*(const float2*)(p0 + ke * 16 + 8), qh[ke][2], ql[ke][2]);
            split2(*(const float2*)(p1 + ke * 16 + 8), qh[ke][3], ql[ke][3]);
        }
    }

    // ---- K,V slab (192 rows x 64) -> smem hi/lo, zero-pad before seq start ----
    {
        const int row0 = pw * 128 - 64;
        #pragma unroll
        for (int it = 0; it < 6; ++it) {
            int idx = tid + it * 256;            // 192*8 = 1536 chunk-units
            int j = idx >> 3, c = idx & 7, g = row0 + j;
            float4 kf0 = make_float4(0.f,0.f,0.f,0.f), kf1 = kf0, vf0 = kf0, vf1 = kf0;
            if (g >= 0) {
                const float* pk = k + base + (size_t)g * 64 + c * 8;
                const float* pv = v + base + (size_t)g * 64 + c * 8;
                kf0 = *(const float4*)pk;  kf1 = *(const float4*)(pk + 4);
                vf0 = *(const float4*)pv;  vf1 = *(const float4*)(pv + 4);
            }
            uint32_t off = SWZ((uint32_t)(j * 128 + c * 16));
            wr_hilo(smc, off, OKH, OKL, kf0, kf1);
            wr_hilo(smc, off, OVH, OVL, vf0, vf1);
        }
    }
    __syncthreads();

    // ---- affine LDSM base addresses ----
    // K addr(ks,ke) = SWZ(((ks*16+rk)<<7) + ke*32 + ck); bits[9:7] = rk&7 (lane-const)
    //   => kaddr[ke] + ks*2048 (lo plane: +24576, folds into immediate)
    const uint32_t rk = (uint32_t)(((lane >> 4) << 3) | (lane & 7));
    const uint32_t ck = (uint32_t)(((lane >> 3) & 1) << 4);
    const uint32_t rv = (uint32_t)((((lane >> 3) & 1) << 3) | (lane & 7));
    const uint32_t cv = (uint32_t)((lane >> 4) << 4);
    const uint32_t wb = (uint32_t)(b * 8192);          // bucket window: slab rows [64b,..)
    const uint32_t xk = (rk & 7) << 4, xv = (rv & 7) << 4;

    uint32_t kaddr[4], vaddr[4];
    #pragma unroll
    for (int ke = 0; ke < 4; ++ke)
        kaddr[ke] = sb + OKH + wb + rk * 128 + ((((uint32_t)ke << 5) | ck) ^ xk);
    #pragma unroll
    for (int etp = 0; etp < 4; ++etp)
        vaddr[etp] = sb + OVH + wb + rv * 128 + ((((uint32_t)etp << 5) | cv) ^ xv);

    float oacc[8][4];
    #pragma unroll
    for (int et = 0; et < 8; ++et)
        #pragma unroll
        for (int x = 0; x < 4; ++x) oacc[et][x] = 0.f;
    float s0 = 0.f, s1 = 0.f;

    // ---- streaming flash loop over window chunks (16 k/v rows each) ----
    #pragma unroll
    for (int ks = 0; ks < 8; ++ks) {
        // chunks 0..3 = previous bucket: skip when padded; below-diagonal chunks unmasked
        if ((ks < nlim) && (wok || ks >= 4)) {
            const bool diag = (ks == nlim - 1);
            const uint32_t ko = (uint32_t)(ks << 11);   // compile-time per unrolled iter

            // --- S chunk: 16 q-rows x 16 cols, K=64 ---
            float a2[8];
            #pragma unroll
            for (int x = 0; x < 8; ++x) a2[x] = 0.f;
            #pragma unroll
            for (int ke = 0; ke < 4; ++ke) {
                uint32_t bh0, bh1, bh2, bh3, bl0, bl1, bl2, bl3;
                LDSM4(bh0, bh1, bh2, bh3, kaddr[ke] + ko);
                LDSM4(bl0, bl1, bl2, bl3, kaddr[ke] + ko + 24576);
                MMA(a2,     qh[ke][0], qh[ke][1], qh[ke][2], qh[ke][3], bh0, bh1);
                MMA(a2,     qh[ke][0], qh[ke][1], qh[ke][2], qh[ke][3], bl0, bl1);
                MMA(a2,     ql[ke][0], ql[ke][1], ql[ke][2], ql[ke][3], bh0, bh1);
                MMA(a2 + 4, qh[ke][0], qh[ke][1], qh[ke][2], qh[ke][3], bh2, bh3);
                MMA(a2 + 4, qh[ke][0], qh[ke][1], qh[ke][2], qh[ke][3], bl2, bl3);
                MMA(a2 + 4, ql[ke][0], ql[ke][1], ql[ke][2], ql[ke][3], bh2, bh3);
            }

            // --- exp (no max subtraction; |logit| << 88) + diagonal mask + pack ---
            uint32_t ph0, ph1, ph2, ph3, pl0, pl1, pl2, pl3;
            {   // cols +0..7
                float e0 = __expf(a2[0]), e1 = __expf(a2[1]);
                float e2 = __expf(a2[2]), e3 = __expf(a2[3]);
                if (diag) { e0 = d00 ? e0 : 0.f; e1 = d01 ? e1 : 0.f; }
                s0 += e0 + e1;  s1 += e2 + e3;
                ph0 = pkbf2(e0, e1); ph1 = pkbf2(e2, e3);
                pl0 = pkbf2(e0 - __uint_as_float(ph0 << 16),
                            e1 - __uint_as_float(ph0 & 0xffff0000u));
                pl1 = pkbf2(e2 - __uint_as_float(ph1 << 16),
                            e3 - __uint_as_float(ph1 & 0xffff0000u));
            }
            {   // cols +8..15
                float e0 = __expf(a2[4]), e1 = __expf(a2[5]);
                float e2 = __expf(a2[6]), e3 = __expf(a2[7]);
                if (diag) { e0 = 0.f; e1 = 0.f; e2 = d00 ? e2 : 0.f; e3 = d01 ? e3 : 0.f; }
                s0 += e0 + e1;  s1 += e2 + e3;
                ph2 = pkbf2(e0, e1); ph3 = pkbf2(e2, e3);
                pl2 = pkbf2(e0 - __uint_as_float(ph2 << 16),
                            e1 - __uint_as_float(ph2 & 0xffff0000u));
                pl3 = pkbf2(e2 - __uint_as_float(ph3 << 16),
                            e3 - __uint_as_float(ph3 & 0xffff0000u));
            }

            // --- PV for this chunk ---
            #pragma unroll
            for (int etp = 0; etp < 4; ++etp) {
                uint32_t bh0, bh1, bh2, bh3, bl0, bl1, bl2, bl3;
                LDSM4T(bh0, bh1, bh2, bh3, vaddr[etp] + ko);
                LDSM4T(bl0, bl1, bl2, bl3, vaddr[etp] + ko + 24576);
                MMA(oacc[2*etp],   ph0, ph1, ph2, ph3, bh0, bh1);
                MMA(oacc[2*etp],   ph0, ph1, ph2, ph3, bl0, bl1);
                MMA(oacc[2*etp],   pl0, pl1, pl2, pl3, bh0, bh1);
                MMA(oacc[2*etp+1], ph0, ph1, ph2, ph3, bh2, bh3);
                MMA(oacc[2*etp+1], ph0, ph1, ph2, ph3, bl2, bl3);
                MMA(oacc[2*etp+1], pl0, pl1, pl2, pl3, bh2, bh3);
            }
        }
    }

    // ---- reduce sums, normalize, store ----
    s0 += __shfl_xor_sync(0xffffffffu, s0, 1);
    s0 += __shfl_xor_sync(0xffffffffu, s0, 2);
    s1 += __shfl_xor_sync(0xffffffffu, s1, 1);
    s1 += __shfl_xor_sync(0xffffffffu, s1, 2);
    const float inv0 = __fdividef(1.f, s0);
    const float inv1 = __fdividef(1.f, s1);

    float* go = out + base + (size_t)(pw * 128 + b * 64) * 64;
    #pragma unroll
    for (int et = 0; et < 8; ++et) {
        *(float2*)(go + r0 * 64 + et * 8 + t2) =
            make_float2(oacc[et][0] * inv0, oacc[et][1] * inv0);
        *(float2*)(go + r1 * 64 + et * 8 + t2) =
            make_float2(oacc[et][2] * inv1, oacc[et][3] * inv1);
    }
}

extern "C" void kernel_launch(void* const* d_in, const int* in_sizes, int n_in,
                              void* d_out, int out_size)
{
    const float* q = (const float*)d_in[0];
    const float* k = (const float*)d_in[1];
    const float* v = (const float*)d_in[2];
    float* o = (float*)d_out;
    cudaFuncSetAttribute(local_attn_hmma,
                         cudaFuncAttributeMaxDynamicSharedMemorySize, SMEM_BYTES);
    dim3 grid(64, 64);   // 64 bucket-pairs x 64 batch*head
    local_attn_hmma<<<grid, 256, SMEM_BYTES>>>(q, k, v, o);
}

// round 15
// speedup vs baseline: 1.1423x; 1.1423x over previous
#include <cuda_runtime.h>
#include <cuda_bf16.h>
#include <cstdint>

// LocalAttention B=8,H=8,T=8192,E=64; 128 buckets of 64; window = prev+cur bucket.
// QK: HMMA bf16 3-pass split (full precision on logits). PV: single-pass fp16 with
// online max-subtraction (p in (0,1] fits fp16; quant err ~4e-4 << 1e-3).
// Two buckets per 256-thread CTA (192-row shared K/V slab), 2 CTAs/SM.

#define SWZ(o) ((o) ^ (((o) >> 3) & 0x70))

// smem planes: 192 rows x 128B each. K hi, K lo (bf16), V (fp16).
#define OKH 0
#define OKL 24576
#define OVH 49152
#define SMEM_BYTES 73728

static __device__ __forceinline__ uint32_t cvta_s(const void* p) {
    uint32_t a;
    asm("{ .reg .u64 t; cvta.to.shared.u64 t, %1; cvt.u32.u64 %0, t; }" : "=r"(a) : "l"(p));
    return a;
}
static __device__ __forceinline__ uint32_t pkbf2(float lo, float hi) {  // first arg -> low half
    uint32_t r;
    asm("cvt.rn.bf16x2.f32 %0, %1, %2;" : "=r"(r) : "f"(hi), "f"(lo));
    return r;
}
static __device__ __forceinline__ uint32_t pkh2(float lo, float hi) {   // fp16x2, first -> low
    uint32_t r;
    asm("cvt.rn.f16x2.f32 %0, %1, %2;" : "=r"(r) : "f"(hi), "f"(lo));
    return r;
}

#define LDSM4(r0,r1,r2,r3,a) \
    asm("ldmatrix.sync.aligned.m8n8.x4.shared.b16 {%0,%1,%2,%3}, [%4];" \
        : "=r"(r0),"=r"(r1),"=r"(r2),"=r"(r3) : "r"(a) : "memory")
#define LDSM4T(r0,r1,r2,r3,a) \
    asm("ldmatrix.sync.aligned.m8n8.x4.trans.shared.b16 {%0,%1,%2,%3}, [%4];" \
        : "=r"(r0),"=r"(r1),"=r"(r2),"=r"(r3) : "r"(a) : "memory")
#define MMA(d,a0,a1,a2,a3,b0,b1) \
    asm("mma.sync.aligned.m16n8k16.row.col.f32.bf16.bf16.f32 " \
        "{%0,%1,%2,%3},{%4,%5,%6,%7},{%8,%9},{%0,%1,%2,%3};" \
        : "+f"((d)[0]),"+f"((d)[1]),"+f"((d)[2]),"+f"((d)[3]) \
        : "r"(a0),"r"(a1),"r"(a2),"r"(a3),"r"(b0),"r"(b1))
#define MMAH(d,a0,a1,a2,a3,b0,b1) \
    asm("mma.sync.aligned.m16n8k16.row.col.f32.f16.f16.f32 " \
        "{%0,%1,%2,%3},{%4,%5,%6,%7},{%8,%9},{%0,%1,%2,%3};" \
        : "+f"((d)[0]),"+f"((d)[1]),"+f"((d)[2]),"+f"((d)[3]) \
        : "r"(a0),"r"(a1),"r"(a2),"r"(a3),"r"(b0),"r"(b1))

static __device__ __forceinline__ void split2(float2 f, uint32_t& h, uint32_t& l) {
    h = pkbf2(f.x, f.y);
    l = pkbf2(f.x - __uint_as_float(h << 16), f.y - __uint_as_float(h & 0xffff0000u));
}

__global__ __launch_bounds__(256, 2)
void local_attn_hmma(const float* __restrict__ q, const float* __restrict__ k,
                     const float* __restrict__ v, float* __restrict__ out)
{
    extern __shared__ char smc[];
    const uint32_t sb = cvta_s(smc);
    const int tid = threadIdx.x, lane = tid & 31, wp = tid >> 5;
    const int pw = blockIdx.x, bh = blockIdx.y;
    const size_t base = (size_t)bh * (8192 * 64);

    const int b  = wp >> 2;             // bucket within pair (0/1)
    const int wq = wp & 3;              // warp within bucket
    const int t2 = (lane & 3) * 2;
    const int lr = lane >> 2;
    const int r0 = wq * 16 + lr, r1 = r0 + 8;   // local q rows (0..63)
    const int nlim = wq + 5;            // causal: chunks ks < wq+5; ks==nlim-1 diagonal
    const bool wok = (pw > 0) || (b > 0);

    const bool d00 = (t2     <= lr);    // diagonal-chunk masks (chunk-invariant)
    const bool d01 = (t2 + 1 <= lr);

    // ---- Q fragments straight from global, hi/lo split (bf16) ----
    uint32_t qh[4][4], ql[4][4];
    {
        const float* gq = q + base + (size_t)(pw * 128 + b * 64) * 64;
        const float* p0 = gq + r0 * 64 + t2;
        const float* p1 = gq + r1 * 64 + t2;
        #pragma unroll
        for (int ke = 0; ke < 4; ++ke) {
            split2(*(const float2*)(p0 + ke * 16),     qh[ke][0], ql[ke][0]);
            split2(*(const float2*)(p1 + ke * 16),     qh[ke][1], ql[ke][1]);
            split2(*(const float2*)(p0 + ke * 16 + 8), qh[ke][2], ql[ke][2]);
            split2(*(const float2*)(p1 + ke * 16 + 8), qh[ke][3], ql[ke][3]);
        }
    }

    // ---- K (bf16 hi/lo) and V (fp16) slab -> smem, zero-pad before seq start ----
    {
        const int row0 = pw * 128 - 64;
        #pragma unroll
        for (int it = 0; it < 6; ++it) {
            int idx = tid + it * 256;            // 192*8 = 1536 chunk-units
            int j = idx >> 3, c = idx & 7, g = row0 + j;
            float4 kf0 = make_float4(0.f,0.f,0.f,0.f), kf1 = kf0, vf0 = kf0, vf1 = kf0;
            if (g >= 0) {
                const float* pk = k + base + (size_t)g * 64 + c * 8;
                const float* pv = v + base + (size_t)g * 64 + c * 8;
                kf0 = *(const float4*)pk;  kf1 = *(const float4*)(pk + 4);
                vf0 = *(const float4*)pv;  vf1 = *(const float4*)(pv + 4);
            }
            uint32_t off = SWZ((uint32_t)(j * 128 + c * 16));
            // K hi/lo bf16 planes
            uint32_t h0 = pkbf2(kf0.x, kf0.y), h1 = pkbf2(kf0.z, kf0.w);
            uint32_t h2 = pkbf2(kf1.x, kf1.y), h3 = pkbf2(kf1.z, kf1.w);
            uint32_t L0 = pkbf2(kf0.x - __uint_as_float(h0 << 16), kf0.y - __uint_as_float(h0 & 0xffff0000u));
            uint32_t L1 = pkbf2(kf0.z - __uint_as_float(h1 << 16), kf0.w - __uint_as_float(h1 & 0xffff0000u));
            uint32_t L2 = pkbf2(kf1.x - __uint_as_float(h2 << 16), kf1.y - __uint_as_float(h2 & 0xffff0000u));
            uint32_t L3 = pkbf2(kf1.z - __uint_as_float(h3 << 16), kf1.w - __uint_as_float(h3 & 0xffff0000u));
            *(uint4*)(smc + OKH + off) = make_uint4(h0, h1, h2, h3);
            *(uint4*)(smc + OKL + off) = make_uint4(L0, L1, L2, L3);
            // V single fp16 plane
            *(uint4*)(smc + OVH + off) = make_uint4(pkh2(vf0.x, vf0.y), pkh2(vf0.z, vf0.w),
                                                    pkh2(vf1.x, vf1.y), pkh2(vf1.z, vf1.w));
        }
    }
    __syncthreads();

    // ---- affine LDSM base addresses (swizzle XOR is lane-const) ----
    const uint32_t rk = (uint32_t)(((lane >> 4) << 3) | (lane & 7));
    const uint32_t ck = (uint32_t)(((lane >> 3) & 1) << 4);
    const uint32_t rv = (uint32_t)((((lane >> 3) & 1) << 3) | (lane & 7));
    const uint32_t cv = (uint32_t)((lane >> 4) << 4);
    const uint32_t wb = (uint32_t)(b * 8192);
    const uint32_t xk = (rk & 7) << 4, xv = (rv & 7) << 4;

    uint32_t kaddr[4], vaddr[4];
    #pragma unroll
    for (int ke = 0; ke < 4; ++ke)
        kaddr[ke] = sb + OKH + wb + rk * 128 + ((((uint32_t)ke << 5) | ck) ^ xk);
    #pragma unroll
    for (int etp = 0; etp < 4; ++etp)
        vaddr[etp] = sb + OVH + wb + rv * 128 + ((((uint32_t)etp << 5) | cv) ^ xv);

    float oacc[8][4];
    #pragma unroll
    for (int et = 0; et < 8; ++et)
        #pragma unroll
        for (int x = 0; x < 4; ++x) oacc[et][x] = 0.f;
    float s0 = 0.f, s1 = 0.f, m0 = -1e30f, m1 = -1e30f;

    // ---- streaming flash loop over window chunks (16 k/v rows each) ----
    #pragma unroll
    for (int ks = 0; ks < 8; ++ks) {
        if ((ks < nlim) && (wok || ks >= 4)) {
            const bool diag = (ks == nlim - 1);
            const uint32_t ko = (uint32_t)(ks << 11);

            // --- S chunk: 16 q-rows x 16 cols, K=64 (bf16 3-pass) ---
            float a2[8];
            #pragma unroll
            for (int x = 0; x < 8; ++x) a2[x] = 0.f;
            #pragma unroll
            for (int ke = 0; ke < 4; ++ke) {
                uint32_t bh0, bh1, bh2, bh3, bl0, bl1, bl2, bl3;
                LDSM4(bh0, bh1, bh2, bh3, kaddr[ke] + ko);
                LDSM4(bl0, bl1, bl2, bl3, kaddr[ke] + ko + 24576);
                MMA(a2,     qh[ke][0], qh[ke][1], qh[ke][2], qh[ke][3], bh0, bh1);
                MMA(a2,     qh[ke][0], qh[ke][1], qh[ke][2], qh[ke][3], bl0, bl1);
                MMA(a2,     ql[ke][0], ql[ke][1], ql[ke][2], ql[ke][3], bh0, bh1);
                MMA(a2 + 4, qh[ke][0], qh[ke][1], qh[ke][2], qh[ke][3], bh2, bh3);
                MMA(a2 + 4, qh[ke][0], qh[ke][1], qh[ke][2], qh[ke][3], bl2, bl3);
                MMA(a2 + 4, ql[ke][0], ql[ke][1], ql[ke][2], ql[ke][3], bh2, bh3);
            }

            // --- diagonal mask BEFORE max (masked -> -1e30 -> exp 0) ---
            if (diag) {
                a2[0] = d00 ? a2[0] : -1e30f;  a2[1] = d01 ? a2[1] : -1e30f;
                a2[4] = -1e30f;                a2[5] = -1e30f;
                a2[6] = d00 ? a2[6] : -1e30f;  a2[7] = d01 ? a2[7] : -1e30f;
            }

            // --- online max + rescale factors ---
            float cm0 = fmaxf(fmaxf(a2[0], a2[1]), fmaxf(a2[4], a2[5]));
            float cm1 = fmaxf(fmaxf(a2[2], a2[3]), fmaxf(a2[6], a2[7]));
            cm0 = fmaxf(cm0, __shfl_xor_sync(0xffffffffu, cm0, 1));
            cm0 = fmaxf(cm0, __shfl_xor_sync(0xffffffffu, cm0, 2));
            cm1 = fmaxf(cm1, __shfl_xor_sync(0xffffffffu, cm1, 1));
            cm1 = fmaxf(cm1, __shfl_xor_sync(0xffffffffu, cm1, 2));
            const float nm0 = fmaxf(m0, cm0), nm1 = fmaxf(m1, cm1);
            const float f0 = __expf(m0 - nm0), f1 = __expf(m1 - nm1);
            m0 = nm0;  m1 = nm1;

            // --- exp (shifted; p in (0,1]) + fp16 pack ---
            float e0 = __expf(a2[0] - nm0), e1 = __expf(a2[1] - nm0);
            float e2 = __expf(a2[2] - nm1), e3 = __expf(a2[3] - nm1);
            float e4 = __expf(a2[4] - nm0), e5 = __expf(a2[5] - nm0);
            float e6 = __expf(a2[6] - nm1), e7 = __expf(a2[7] - nm1);
            s0 = s0 * f0 + e0 + e1 + e4 + e5;
            s1 = s1 * f1 + e2 + e3 + e6 + e7;
            const uint32_t ph0 = pkh2(e0, e1), ph1 = pkh2(e2, e3);
            const uint32_t ph2 = pkh2(e4, e5), ph3 = pkh2(e6, e7);

            // --- rescale output accumulators ---
            #pragma unroll
            for (int et = 0; et < 8; ++et) {
                oacc[et][0] *= f0;  oacc[et][1] *= f0;
                oacc[et][2] *= f1;  oacc[et][3] *= f1;
            }

            // --- PV: single fp16 pass ---
            #pragma unroll
            for (int etp = 0; etp < 4; ++etp) {
                uint32_t bv0, bv1, bv2, bv3;
                LDSM4T(bv0, bv1, bv2, bv3, vaddr[etp] + ko);
                MMAH(oacc[2*etp],   ph0, ph1, ph2, ph3, bv0, bv1);
                MMAH(oacc[2*etp+1], ph0, ph1, ph2, ph3, bv2, bv3);
            }
        }
    }

    // ---- reduce sums, normalize, store (max cancels in normalization) ----
    s0 += __shfl_xor_sync(0xffffffffu, s0, 1);
    s0 += __shfl_xor_sync(0xffffffffu, s0, 2);
    s1 += __shfl_xor_sync(0xffffffffu, s1, 1);
    s1 += __shfl_xor_sync(0xffffffffu, s1, 2);
    const float inv0 = __fdividef(1.f, s0);
    const float inv1 = __fdividef(1.f, s1);

    float* go = out + base + (size_t)(pw * 128 + b * 64) * 64;
    #pragma unroll
    for (int et = 0; et < 8; ++et) {
        *(float2*)(go + r0 * 64 + et * 8 + t2) =
            make_float2(oacc[et][0] * inv0, oacc[et][1] * inv0);
        *(float2*)(go + r1 * 64 + et * 8 + t2) =
            make_float2(oacc[et][2] * inv1, oacc[et][3] * inv1);
    }
}

extern "C" void kernel_launch(void* const* d_in, const int* in_sizes, int n_in,
                              void* d_out, int out_size)
{
    const float* q = (const float*)d_in[0];
    const float* k = (const float*)d_in[1];
    const float* v = (const float*)d_in[2];
    float* o = (float*)d_out;
    cudaFuncSetAttribute(local_attn_hmma,
                         cudaFuncAttributeMaxDynamicSharedMemorySize, SMEM_BYTES);
    dim3 grid(64, 64);   // 64 bucket-pairs x 64 batch*head
    local_attn_hmma<<<grid, 256, SMEM_BYTES>>>(q, k, v, o);
}